// round 16
// baseline (speedup 1.0000x reference)
#include <cuda_runtime.h>
#include <math.h>

#define Bsz 4
#define Ssz 2048
#define Dsz 1024
#define Hsz 1024
#define TOK (Bsz*Ssz)   // 8192

#define GRU_CTAS 128
#define GRU_JPB  8      // hidden units per CTA (1024 / 128)
#define GRU_SMEM_BYTES ((24*1024 + 4*1024) * 4)  // 24 weight rows + h buffer

// ---------------- scratch (static device arrays; no allocation) ----------------
__device__ float d_xn[TOK*Dsz];
__device__ float d_xi[TOK*3*Hsz];
__device__ float d_y [TOK*Hsz];
__device__ float d_x1[TOK*Dsz];
__device__ float d_m0[TOK*Dsz];
__device__ float d_m1[TOK*Dsz];
__device__ float d_c1[TOK*Dsz];
__device__ float d_c2[TOK*512];
__device__ float d_c3[TOK*256];
__device__ float d_tf[TOK];
__device__ float d_gc[Bsz*Dsz];
__device__ float d_g1[Bsz*512];
__device__ float d_g2[Bsz*256];
__device__ float d_gg[Bsz];
__device__ float d_f1[TOK*4096];
__device__ float d_h [2*Bsz*Hsz];
__device__ unsigned int d_bar;

// ---------------- helpers ----------------
__device__ __forceinline__ float gelu_f(float v) {
    return 0.5f * v * (1.0f + erff(v * 0.7071067811865475f));
}
__device__ __forceinline__ float sigm_f(float v) {
    return 1.0f / (1.0f + expf(-v));
}
// packed fp32x2 FMA (FFMA2): d = a*b + d, elementwise on two packed floats
__device__ __forceinline__ void ffma2(unsigned long long &d,
                                      unsigned long long a,
                                      unsigned long long b) {
    asm volatile("fma.rn.f32x2 %0, %1, %2, %0;" : "+l"(d) : "l"(a), "l"(b));
}
__device__ __forceinline__ unsigned long long dup2(float x) {
    unsigned long long r;
    unsigned int xu = __float_as_uint(x);
    asm("mov.b64 %0, {%1, %1};" : "=l"(r) : "r"(xu));
    return r;
}

// ---------------- LayerNorm: one CTA per 1024-wide row ----------------
__global__ void __launch_bounds__(256) ln_k(const float* __restrict__ x,
                                            const float* __restrict__ g,
                                            const float* __restrict__ b,
                                            float* __restrict__ y)
{
    __shared__ float red_s[8];
    __shared__ float red_q[8];
    const int row  = blockIdx.x;
    const int tid  = threadIdx.x;
    const int lane = tid & 31;
    const int warp = tid >> 5;

    float4 v = ((const float4*)(x + (size_t)row * Dsz))[tid];
    float s = v.x + v.y + v.z + v.w;
    float q = v.x*v.x + v.y*v.y + v.z*v.z + v.w*v.w;
    #pragma unroll
    for (int o = 16; o > 0; o >>= 1) {
        s += __shfl_xor_sync(0xffffffffu, s, o);
        q += __shfl_xor_sync(0xffffffffu, q, o);
    }
    if (lane == 0) { red_s[warp] = s; red_q[warp] = q; }
    __syncthreads();
    float ts = 0.f, tq = 0.f;
    #pragma unroll
    for (int i = 0; i < 8; i++) { ts += red_s[i]; tq += red_q[i]; }
    const float mean = ts * (1.0f / (float)Dsz);
    const float var  = tq * (1.0f / (float)Dsz) - mean * mean;
    const float rs   = rsqrtf(var + 1e-5f);

    float4 gv = ((const float4*)g)[tid];
    float4 bv = ((const float4*)b)[tid];
    float4 o;
    o.x = (v.x - mean) * rs * gv.x + bv.x;
    o.y = (v.y - mean) * rs * gv.y + bv.y;
    o.z = (v.z - mean) * rs * gv.z + bv.z;
    o.w = (v.w - mean) * rs * gv.w + bv.w;
    ((float4*)(y + (size_t)row * Dsz))[tid] = o;
}

// ---------------- SGEMM NT (FFMA2 + double-buffered smem) ----------------
// C = act(A[M,K] * B[N,K]^T + bias) (+resid). BM=BN=128, BK=8, 256 threads,
// 8x8 per thread, accumulators packed f32x2 along M.
#define SGEMM_COMPUTE(S)                                                     \
    _Pragma("unroll")                                                        \
    for (int kk = 0; kk < 8; kk++) {                                         \
        const ulonglong2 a01 = *(const ulonglong2*)&As[S][kk][ty];           \
        const ulonglong2 a23 = *(const ulonglong2*)&As[S][kk][ty+4];         \
        const float4 b0 = *(const float4*)&Bs[S][kk][tx];                    \
        const float4 b1 = *(const float4*)&Bs[S][kk][tx+4];                  \
        unsigned long long aa[4] = {a01.x, a01.y, a23.x, a23.y};             \
        unsigned long long bb[8];                                            \
        bb[0] = dup2(b0.x); bb[1] = dup2(b0.y);                              \
        bb[2] = dup2(b0.z); bb[3] = dup2(b0.w);                              \
        bb[4] = dup2(b1.x); bb[5] = dup2(b1.y);                              \
        bb[6] = dup2(b1.z); bb[7] = dup2(b1.w);                              \
        _Pragma("unroll")                                                    \
        for (int i2 = 0; i2 < 4; i2++)                                       \
            _Pragma("unroll")                                                \
            for (int j = 0; j < 8; j++)                                      \
                ffma2(acc2[i2][j], aa[i2], bb[j]);                           \
    }

__global__ void __launch_bounds__(256, 2) sgemm_nt(int M, int N, int K,
    const float* __restrict__ A, const float* __restrict__ B,
    const float* __restrict__ bias, const float* __restrict__ resid,
    float* __restrict__ C, int act)
{
    __shared__ float As[2][8][128];
    __shared__ float Bs[2][8][128];
    const int tid  = threadIdx.x;
    const int bm   = blockIdx.y * 128;
    const int bn   = blockIdx.x * 128;
    const int lrow = tid >> 1;
    const int lk   = (tid & 1) * 4;
    const int arow = bm + lrow;
    const bool aok = arow < M;
    const float* Ap = A + (size_t)(aok ? arow : 0) * K + lk;
    const float* Bp = B + (size_t)(bn + lrow) * K + lk;
    const int tx = (tid & 15) * 8;
    const int ty = (tid >> 4) * 8;

    unsigned long long acc2[4][8];
    #pragma unroll
    for (int i = 0; i < 4; i++)
        #pragma unroll
        for (int j = 0; j < 8; j++) acc2[i][j] = 0ull;

    // prologue: stage 0
    {
        float4 av = aok ? *(const float4*)(Ap) : make_float4(0.f,0.f,0.f,0.f);
        float4 bv = *(const float4*)(Bp);
        As[0][lk+0][lrow]=av.x; As[0][lk+1][lrow]=av.y; As[0][lk+2][lrow]=av.z; As[0][lk+3][lrow]=av.w;
        Bs[0][lk+0][lrow]=bv.x; Bs[0][lk+1][lrow]=bv.y; Bs[0][lk+2][lrow]=bv.z; Bs[0][lk+3][lrow]=bv.w;
    }
    __syncthreads();

    int buf = 0;
    for (int k0 = 8; k0 < K; k0 += 8) {
        float4 av = aok ? *(const float4*)(Ap + k0) : make_float4(0.f,0.f,0.f,0.f);
        float4 bv = *(const float4*)(Bp + k0);
        SGEMM_COMPUTE(buf);
        const int nb = buf ^ 1;
        As[nb][lk+0][lrow]=av.x; As[nb][lk+1][lrow]=av.y; As[nb][lk+2][lrow]=av.z; As[nb][lk+3][lrow]=av.w;
        Bs[nb][lk+0][lrow]=bv.x; Bs[nb][lk+1][lrow]=bv.y; Bs[nb][lk+2][lrow]=bv.z; Bs[nb][lk+3][lrow]=bv.w;
        __syncthreads();
        buf = nb;
    }
    SGEMM_COMPUTE(buf);

    #pragma unroll
    for (int i2 = 0; i2 < 4; i2++) {
        #pragma unroll
        for (int half = 0; half < 2; half++) {
            const int row = bm + ty + 2*i2 + half;
            if (row >= M) continue;
            const size_t off = (size_t)row * N + bn + tx;
            #pragma unroll
            for (int j = 0; j < 8; j++) {
                const unsigned long long p = acc2[i2][j];
                const float a = half ? __uint_as_float((unsigned int)(p >> 32))
                                     : __uint_as_float((unsigned int)(p));
                float v = a + bias[bn + tx + j];
                if (act == 1)      v = gelu_f(v);
                else if (act == 2) v = sigm_f(v);
                if (resid) v += resid[off + j];
                C[off + j] = v;
            }
        }
    }
}

// ---------------- row dot (N==1): out[m] = sigmoid(dot(A[m],w)+b0) ----------------
__global__ void __launch_bounds__(256) rowdot_k(int M, int K,
    const float* __restrict__ A, const float* __restrict__ w,
    const float* __restrict__ b0, float* __restrict__ out)
{
    const int warp = threadIdx.x >> 5;
    const int lane = threadIdx.x & 31;
    const int row  = blockIdx.x * 8 + warp;
    if (row >= M) return;
    const float* a = A + (size_t)row * K;
    float s = 0.f;
    for (int k = lane; k < K; k += 32) s = fmaf(a[k], w[k], s);
    #pragma unroll
    for (int o = 16; o > 0; o >>= 1) s += __shfl_xor_sync(0xffffffffu, s, o);
    if (lane == 0) out[row] = sigm_f(s + b0[0]);
}

// ---------------- batch mean over S: gc[b,d] = mean_s x[b,s,d] ----------------
__global__ void __launch_bounds__(256) batchmean_k(const float* __restrict__ x,
                                                   float* __restrict__ gc)
{
    const int idx = blockIdx.x * 256 + threadIdx.x;   // 0..4095
    if (idx >= Bsz * Dsz) return;
    const int b = idx >> 10, d = idx & 1023;
    const float* p = x + (size_t)b * Ssz * Dsz + d;
    float s0 = 0.f, s1 = 0.f, s2 = 0.f, s3 = 0.f;
    for (int t = 0; t < Ssz; t += 4) {
        s0 += p[(size_t)(t+0) * Dsz];
        s1 += p[(size_t)(t+1) * Dsz];
        s2 += p[(size_t)(t+2) * Dsz];
        s3 += p[(size_t)(t+3) * Dsz];
    }
    gc[idx] = (s0 + s1 + s2 + s3) * (1.0f / (float)Ssz);
}

// ---------------- mobius update: out = in + coup * twist(in) ----------------
__global__ void __launch_bounds__(256) mobius_k(const float* __restrict__ in,
    const float* __restrict__ tf, const float* __restrict__ g,
    const float* __restrict__ arng, float* __restrict__ out)
{
    const int row = blockIdx.x;           // 0..8191 = b*S+t
    const int b   = row >> 11;
    const float ar = arng[0];
    const float combined = 0.7f * g[b] + 0.3f * tf[row];
    const float coup = 0.1f + ar * (combined - 0.5f) * 2.0f;
    const float* ip = in  + (size_t)row * Dsz;
    float*       op = out + (size_t)row * Dsz;
    for (int i = threadIdx.x; i < Dsz; i += 256) {
        const int j = (i + 512) & 1023;
        const float sgn = (i < 256 || i >= 768) ? 1.0f : -1.0f;
        op[i] = ip[i] + coup * sgn * ip[j];
    }
}

// ---------------- elementwise add (float4) ----------------
__global__ void __launch_bounds__(256) add_k(const float* __restrict__ a,
                                             const float* __restrict__ b,
                                             float* __restrict__ c, int n4)
{
    const int i = blockIdx.x * 256 + threadIdx.x;
    if (i >= n4) return;
    float4 av = ((const float4*)a)[i];
    float4 bv = ((const float4*)b)[i];
    float4 cv;
    cv.x = av.x + bv.x; cv.y = av.y + bv.y; cv.z = av.z + bv.z; cv.w = av.w + bv.w;
    ((float4*)c)[i] = cv;
}

// ---------------- GRU init: zero hidden ping-pong + barrier counter ----------------
__global__ void gru_init_k()
{
    const int i = blockIdx.x * 256 + threadIdx.x;
    if (i < 2 * Bsz * Hsz) d_h[i] = 0.f;
    if (i == 0) d_bar = 0u;
}

// ---------------- persistent GRU recurrence ----------------
// 128 CTAs x 256 threads. Each CTA holds 24 W_hh rows (3 gates x 8 units) in SMEM.
// Each warp owns one hidden unit j; per step computes r/z/n dots for 4 batches.
// Barrier: release-atomic arrival + acquire poll; next-step xi prefetch is issued
// between release and poll to hide its DRAM latency under the barrier wait.
__global__ void __launch_bounds__(256, 1) gru_kernel(const float* __restrict__ xi,
    const float* __restrict__ Whh, const float* __restrict__ bhh,
    float* __restrict__ y)
{
    extern __shared__ float sm[];
    float* ws = sm;                 // 24*1024 weights
    float* hs = sm + 24 * 1024;     // 4*1024 hidden state
    const int tid   = threadIdx.x;
    const int warp  = tid >> 5;
    const int lane  = tid & 31;
    const int jbase = blockIdx.x * GRU_JPB;
    const int jg    = jbase + warp;

    // stage weights once (rows g*H + jbase + jw, g=0..2, jw=0..7)
    for (int idx = tid; idx < 24 * 256; idx += 256) {
        const int rl = idx >> 8;          // 0..23
        const int c4 = idx & 255;
        const int g  = rl >> 3, jw = rl & 7;
        const float4 v = *(const float4*)(Whh + (size_t)(g * Hsz + jbase + jw) * Hsz + c4 * 4);
        *(float4*)(ws + rl * Hsz + c4 * 4) = v;
    }
    const float bh0 = bhh[0 * Hsz + jg];
    const float bh1 = bhh[1 * Hsz + jg];
    const float bh2 = bhh[2 * Hsz + jg];
    __syncthreads();

    const float4* wr4 = (const float4*)(ws + (0 * GRU_JPB + warp) * Hsz);
    const float4* wz4 = (const float4*)(ws + (1 * GRU_JPB + warp) * Hsz);
    const float4* wn4 = (const float4*)(ws + (2 * GRU_JPB + warp) * Hsz);
    const float4* hs4 = (const float4*)hs;

    // prefetch xi for t = 0 (lanes 0..11: g = lane>>2, b = lane&3)
    float vxi = 0.f;
    if (lane < 12) {
        const int g = lane >> 2, b = lane & 3;
        vxi = xi[(size_t)(b * Ssz + 0) * (3 * Hsz) + g * Hsz + jg];
    }

    for (int t = 0; t < Ssz; t++) {
        // stage h (written by all CTAs last step) -> SMEM; .cg to bypass stale L1
        const float4* hp = (const float4*)(d_h + (t & 1) * Bsz * Hsz);
        for (int i = tid; i < Bsz * Hsz / 4; i += 256)
            *(float4*)(hs + i * 4) = __ldcg(hp + i);
        __syncthreads();

        float acc[3][4];
        #pragma unroll
        for (int g = 0; g < 3; g++)
            #pragma unroll
            for (int b = 0; b < 4; b++) acc[g][b] = 0.f;

        #pragma unroll
        for (int it = 0; it < 8; it++) {
            const int kq = lane + it * 32;          // float4 index 0..255
            const float4 wr = wr4[kq];
            const float4 wz = wz4[kq];
            const float4 wn = wn4[kq];
            #pragma unroll
            for (int b = 0; b < 4; b++) {
                const float4 h = hs4[b * 256 + kq];
                acc[0][b] += wr.x * h.x + wr.y * h.y + wr.z * h.z + wr.w * h.w;
                acc[1][b] += wz.x * h.x + wz.y * h.y + wz.z * h.z + wz.w * h.w;
                acc[2][b] += wn.x * h.x + wn.y * h.y + wn.z * h.z + wn.w * h.w;
            }
        }

        // warp reductions
        #pragma unroll
        for (int g = 0; g < 3; g++)
            #pragma unroll
            for (int b = 0; b < 4; b++)
                #pragma unroll
                for (int o = 16; o > 0; o >>= 1)
                    acc[g][b] += __shfl_xor_sync(0xffffffffu, acc[g][b], o);

        float* hn_out = d_h + ((t & 1) ^ 1) * Bsz * Hsz;
        #pragma unroll
        for (int b = 0; b < 4; b++) {
            const float xr = __shfl_sync(0xffffffffu, vxi, 0 * 4 + b);
            const float xz = __shfl_sync(0xffffffffu, vxi, 1 * 4 + b);
            const float xn = __shfl_sync(0xffffffffu, vxi, 2 * 4 + b);
            if (lane == b) {
                const float r = 1.f / (1.f + expf(-(xr + acc[0][b] + bh0)));
                const float z = 1.f / (1.f + expf(-(xz + acc[1][b] + bh1)));
                const float n = tanhf(xn + r * (acc[2][b] + bh2));
                const float hold = hs[b * Hsz + jg];
                const float hv = (1.f - z) * n + z * hold;
                hn_out[b * Hsz + jg] = hv;
                y[(size_t)(b * Ssz + t) * Hsz + jg] = hv;
            }
        }

        if (t < Ssz - 1) {
            __syncthreads();   // all warps' h writes done + hs reads complete
            // arrival: release-atomic (fence folded into the op)
            if (tid == 0)
                asm volatile("red.release.gpu.global.add.u32 [%0], %1;"
                             :: "l"(&d_bar), "r"(1u) : "memory");
            // overlap next step's xi DRAM load with the barrier wait
            float vxin = 0.f;
            if (lane < 12) {
                const int g = lane >> 2, b = lane & 3;
                vxin = xi[(size_t)(b * Ssz + (t + 1)) * (3 * Hsz) + g * Hsz + jg];
            }
            if (tid == 0) {
                const unsigned int target = (unsigned)GRU_CTAS * (unsigned)(t + 1);
                unsigned int v;
                do {
                    asm volatile("ld.acquire.gpu.u32 %0, [%1];" : "=r"(v) : "l"(&d_bar) : "memory");
                } while (v < target);
            }
            __syncthreads();
            vxi = vxin;
        }
    }
}

// ---------------- host launcher ----------------
extern "C" void kernel_launch(void* const* d_in, const int* in_sizes, int n_in,
                              void* d_out, int out_size)
{
    const float* x    = (const float*)d_in[0];
    const float* g1w  = (const float*)d_in[1];
    const float* g1b  = (const float*)d_in[2];
    const float* g2w  = (const float*)d_in[3];
    const float* g2b  = (const float*)d_in[4];
    const float* Wih0 = (const float*)d_in[5];
    const float* Whh0 = (const float*)d_in[6];
    const float* bih0 = (const float*)d_in[7];
    const float* bhh0 = (const float*)d_in[8];
    const float* Wih1 = (const float*)d_in[9];
    const float* Whh1 = (const float*)d_in[10];
    const float* bih1 = (const float*)d_in[11];
    const float* bhh1 = (const float*)d_in[12];
    const float* cw1  = (const float*)d_in[13];
    const float* cb1  = (const float*)d_in[14];
    const float* cw2  = (const float*)d_in[15];
    const float* cb2  = (const float*)d_in[16];
    const float* cw3  = (const float*)d_in[17];
    const float* cb3  = (const float*)d_in[18];
    const float* cw4  = (const float*)d_in[19];
    const float* cb4  = (const float*)d_in[20];
    const float* gw1  = (const float*)d_in[21];
    const float* gb1  = (const float*)d_in[22];
    const float* gw2  = (const float*)d_in[23];
    const float* gb2  = (const float*)d_in[24];
    const float* gw3  = (const float*)d_in[25];
    const float* gb3  = (const float*)d_in[26];
    const float* arng = (const float*)d_in[27];
    const float* fw1  = (const float*)d_in[28];
    const float* fb1  = (const float*)d_in[29];
    const float* fw2  = (const float*)d_in[30];
    const float* fb2  = (const float*)d_in[31];
    float* out = (float*)d_out;

    float *xn, *xi, *y, *x1, *m0, *m1, *c1, *c2, *c3, *tf, *gc, *g1, *g2, *gg, *f1;
    cudaGetSymbolAddress((void**)&xn, d_xn);
    cudaGetSymbolAddress((void**)&xi, d_xi);
    cudaGetSymbolAddress((void**)&y,  d_y);
    cudaGetSymbolAddress((void**)&x1, d_x1);
    cudaGetSymbolAddress((void**)&m0, d_m0);
    cudaGetSymbolAddress((void**)&m1, d_m1);
    cudaGetSymbolAddress((void**)&c1, d_c1);
    cudaGetSymbolAddress((void**)&c2, d_c2);
    cudaGetSymbolAddress((void**)&c3, d_c3);
    cudaGetSymbolAddress((void**)&tf, d_tf);
    cudaGetSymbolAddress((void**)&gc, d_gc);
    cudaGetSymbolAddress((void**)&g1, d_g1);
    cudaGetSymbolAddress((void**)&g2, d_g2);
    cudaGetSymbolAddress((void**)&gg, d_gg);
    cudaGetSymbolAddress((void**)&f1, d_f1);

    cudaFuncSetAttribute(gru_kernel, cudaFuncAttributeMaxDynamicSharedMemorySize,
                         GRU_SMEM_BYTES);

    const int n4   = TOK * Dsz / 4;
    const int addg = (n4 + 255) / 256;

    // ---- Block 1: LN -> GRU x2 -> residual ----
    ln_k<<<TOK, 256>>>(x, g1w, g1b, xn);
    sgemm_nt<<<dim3(3072/128, TOK/128), 256>>>(TOK, 3072, 1024, xn, Wih0, bih0, nullptr, xi, 0);
    gru_init_k<<<32, 256>>>();
    gru_kernel<<<GRU_CTAS, 256, GRU_SMEM_BYTES>>>(xi, Whh0, bhh0, y);
    sgemm_nt<<<dim3(3072/128, TOK/128), 256>>>(TOK, 3072, 1024, y, Wih1, bih1, nullptr, xi, 0);
    gru_init_k<<<32, 256>>>();
    gru_kernel<<<GRU_CTAS, 256, GRU_SMEM_BYTES>>>(xi, Whh1, bhh1, y);
    add_k<<<addg, 256>>>(x, y, x1, n4);

    // ---- Block 2: LN -> adaptive mobius -> residual ----
    ln_k<<<TOK, 256>>>(x1, g2w, g2b, xn);
    batchmean_k<<<(Bsz*Dsz + 255)/256, 256>>>(xn, gc);
    sgemm_nt<<<dim3(512/128, 1), 256>>>(Bsz, 512, 1024, gc, gw1, gb1, nullptr, g1, 1);
    sgemm_nt<<<dim3(256/128, 1), 256>>>(Bsz, 256, 512,  g1, gw2, gb2, nullptr, g2, 1);
    rowdot_k<<<1, 256>>>(Bsz, 256, g2, gw3, gb3, gg);

    float* cur = xn;
    float* nxt = m0;
    for (int cyc = 0; cyc < 3; cyc++) {
        sgemm_nt<<<dim3(1024/128, TOK/128), 256>>>(TOK, 1024, 1024, cur, cw1, cb1, nullptr, c1, 1);
        sgemm_nt<<<dim3(512/128,  TOK/128), 256>>>(TOK, 512,  1024, c1,  cw2, cb2, nullptr, c2, 1);
        sgemm_nt<<<dim3(256/128,  TOK/128), 256>>>(TOK, 256,  512,  c2,  cw3, cb3, nullptr, c3, 1);
        rowdot_k<<<(TOK + 7)/8, 256>>>(TOK, 256, c3, cw4, cb4, tf);
        mobius_k<<<TOK, 256>>>(cur, tf, gg, arng, nxt);
        cur = nxt;
        nxt = (cyc == 0) ? m1 : m0;
    }
    add_k<<<addg, 256>>>(x1, cur, x1, n4);   // x2 = x1 + mobius (in-place)

    // ---- Block 3: FFN residual ----
    sgemm_nt<<<dim3(4096/128, TOK/128), 256>>>(TOK, 4096, 1024, x1, fw1, fb1, nullptr, f1, 1);
    sgemm_nt<<<dim3(1024/128, TOK/128), 256>>>(TOK, 1024, 4096, f1, fw2, fb2, x1, out, 0);
}

// round 17
// speedup vs baseline: 1.0046x; 1.0046x over previous
#include <cuda_runtime.h>
#include <math.h>

#define Bsz 4
#define Ssz 2048
#define Dsz 1024
#define Hsz 1024
#define TOK (Bsz*Ssz)   // 8192

#define GRU_CTAS 128
#define GRU_JPB  8      // hidden units per CTA (1024 / 128)
#define GRU_SMEM_BYTES ((24*1024 + 4*1024) * 4)  // 24 weight rows + h buffer

// ---------------- scratch (static device arrays; no allocation) ----------------
__device__ float d_xn[TOK*Dsz];
__device__ float d_xi[TOK*3*Hsz];
__device__ float d_y [TOK*Hsz];
__device__ float d_x1[TOK*Dsz];
__device__ float d_m0[TOK*Dsz];
__device__ float d_m1[TOK*Dsz];
__device__ float d_c1[TOK*Dsz];
__device__ float d_c2[TOK*512];
__device__ float d_c3[TOK*256];
__device__ float d_tf[TOK];
__device__ float d_gc[Bsz*Dsz];
__device__ float d_g1[Bsz*512];
__device__ float d_g2[Bsz*256];
__device__ float d_gg[Bsz];
__device__ float d_f1[TOK*4096];
__device__ float d_h [2*Bsz*Hsz];
__device__ unsigned int d_bar;

// ---------------- helpers ----------------
__device__ __forceinline__ float gelu_f(float v) {
    return 0.5f * v * (1.0f + erff(v * 0.7071067811865475f));
}
__device__ __forceinline__ float sigm_f(float v) {
    return 1.0f / (1.0f + expf(-v));
}
// packed fp32x2 FMA (FFMA2): d = a*b + d, elementwise on two packed floats
__device__ __forceinline__ void ffma2(unsigned long long &d,
                                      unsigned long long a,
                                      unsigned long long b) {
    asm volatile("fma.rn.f32x2 %0, %1, %2, %0;" : "+l"(d) : "l"(a), "l"(b));
}
__device__ __forceinline__ unsigned long long dup2(float x) {
    unsigned long long r;
    unsigned int xu = __float_as_uint(x);
    asm("mov.b64 %0, {%1, %1};" : "=l"(r) : "r"(xu));
    return r;
}

// ---------------- LayerNorm: one CTA per 1024-wide row ----------------
__global__ void __launch_bounds__(256) ln_k(const float* __restrict__ x,
                                            const float* __restrict__ g,
                                            const float* __restrict__ b,
                                            float* __restrict__ y)
{
    __shared__ float red_s[8];
    __shared__ float red_q[8];
    const int row  = blockIdx.x;
    const int tid  = threadIdx.x;
    const int lane = tid & 31;
    const int warp = tid >> 5;

    float4 v = ((const float4*)(x + (size_t)row * Dsz))[tid];
    float s = v.x + v.y + v.z + v.w;
    float q = v.x*v.x + v.y*v.y + v.z*v.z + v.w*v.w;
    #pragma unroll
    for (int o = 16; o > 0; o >>= 1) {
        s += __shfl_xor_sync(0xffffffffu, s, o);
        q += __shfl_xor_sync(0xffffffffu, q, o);
    }
    if (lane == 0) { red_s[warp] = s; red_q[warp] = q; }
    __syncthreads();
    float ts = 0.f, tq = 0.f;
    #pragma unroll
    for (int i = 0; i < 8; i++) { ts += red_s[i]; tq += red_q[i]; }
    const float mean = ts * (1.0f / (float)Dsz);
    const float var  = tq * (1.0f / (float)Dsz) - mean * mean;
    const float rs   = rsqrtf(var + 1e-5f);

    float4 gv = ((const float4*)g)[tid];
    float4 bv = ((const float4*)b)[tid];
    float4 o;
    o.x = (v.x - mean) * rs * gv.x + bv.x;
    o.y = (v.y - mean) * rs * gv.y + bv.y;
    o.z = (v.z - mean) * rs * gv.z + bv.z;
    o.w = (v.w - mean) * rs * gv.w + bv.w;
    ((float4*)(y + (size_t)row * Dsz))[tid] = o;
}

// ---------------- SGEMM NT (FFMA2 + double-buffered smem) ----------------
// C = act(A[M,K] * B[N,K]^T + bias) (+resid). BM=BN=128, BK=8, 256 threads,
// 8x8 per thread, accumulators packed f32x2 along M.
#define SGEMM_COMPUTE(S)                                                     \
    _Pragma("unroll")                                                        \
    for (int kk = 0; kk < 8; kk++) {                                         \
        const ulonglong2 a01 = *(const ulonglong2*)&As[S][kk][ty];           \
        const ulonglong2 a23 = *(const ulonglong2*)&As[S][kk][ty+4];         \
        const float4 b0 = *(const float4*)&Bs[S][kk][tx];                    \
        const float4 b1 = *(const float4*)&Bs[S][kk][tx+4];                  \
        unsigned long long aa[4] = {a01.x, a01.y, a23.x, a23.y};             \
        unsigned long long bb[8];                                            \
        bb[0] = dup2(b0.x); bb[1] = dup2(b0.y);                              \
        bb[2] = dup2(b0.z); bb[3] = dup2(b0.w);                              \
        bb[4] = dup2(b1.x); bb[5] = dup2(b1.y);                              \
        bb[6] = dup2(b1.z); bb[7] = dup2(b1.w);                              \
        _Pragma("unroll")                                                    \
        for (int i2 = 0; i2 < 4; i2++)                                       \
            _Pragma("unroll")                                                \
            for (int j = 0; j < 8; j++)                                      \
                ffma2(acc2[i2][j], aa[i2], bb[j]);                           \
    }

__global__ void __launch_bounds__(256, 2) sgemm_nt(int M, int N, int K,
    const float* __restrict__ A, const float* __restrict__ B,
    const float* __restrict__ bias, const float* __restrict__ resid,
    float* __restrict__ C, int act)
{
    __shared__ float As[2][8][128];
    __shared__ float Bs[2][8][128];
    const int tid  = threadIdx.x;
    const int bm   = blockIdx.y * 128;
    const int bn   = blockIdx.x * 128;
    const int lrow = tid >> 1;
    const int lk   = (tid & 1) * 4;
    const int arow = bm + lrow;
    const bool aok = arow < M;
    const float* Ap = A + (size_t)(aok ? arow : 0) * K + lk;
    const float* Bp = B + (size_t)(bn + lrow) * K + lk;
    const int tx = (tid & 15) * 8;
    const int ty = (tid >> 4) * 8;

    unsigned long long acc2[4][8];
    #pragma unroll
    for (int i = 0; i < 4; i++)
        #pragma unroll
        for (int j = 0; j < 8; j++) acc2[i][j] = 0ull;

    // prologue: stage 0
    {
        float4 av = aok ? *(const float4*)(Ap) : make_float4(0.f,0.f,0.f,0.f);
        float4 bv = *(const float4*)(Bp);
        As[0][lk+0][lrow]=av.x; As[0][lk+1][lrow]=av.y; As[0][lk+2][lrow]=av.z; As[0][lk+3][lrow]=av.w;
        Bs[0][lk+0][lrow]=bv.x; Bs[0][lk+1][lrow]=bv.y; Bs[0][lk+2][lrow]=bv.z; Bs[0][lk+3][lrow]=bv.w;
    }
    __syncthreads();

    int buf = 0;
    for (int k0 = 8; k0 < K; k0 += 8) {
        float4 av = aok ? *(const float4*)(Ap + k0) : make_float4(0.f,0.f,0.f,0.f);
        float4 bv = *(const float4*)(Bp + k0);
        SGEMM_COMPUTE(buf);
        const int nb = buf ^ 1;
        As[nb][lk+0][lrow]=av.x; As[nb][lk+1][lrow]=av.y; As[nb][lk+2][lrow]=av.z; As[nb][lk+3][lrow]=av.w;
        Bs[nb][lk+0][lrow]=bv.x; Bs[nb][lk+1][lrow]=bv.y; Bs[nb][lk+2][lrow]=bv.z; Bs[nb][lk+3][lrow]=bv.w;
        __syncthreads();
        buf = nb;
    }
    SGEMM_COMPUTE(buf);

    #pragma unroll
    for (int i2 = 0; i2 < 4; i2++) {
        #pragma unroll
        for (int half = 0; half < 2; half++) {
            const int row = bm + ty + 2*i2 + half;
            if (row >= M) continue;
            const size_t off = (size_t)row * N + bn + tx;
            #pragma unroll
            for (int j = 0; j < 8; j++) {
                const unsigned long long p = acc2[i2][j];
                const float a = half ? __uint_as_float((unsigned int)(p >> 32))
                                     : __uint_as_float((unsigned int)(p));
                float v = a + bias[bn + tx + j];
                if (act == 1)      v = gelu_f(v);
                else if (act == 2) v = sigm_f(v);
                if (resid) v += resid[off + j];
                C[off + j] = v;
            }
        }
    }
}

// ---------------- row dot (N==1): out[m] = sigmoid(dot(A[m],w)+b0) ----------------
__global__ void __launch_bounds__(256) rowdot_k(int M, int K,
    const float* __restrict__ A, const float* __restrict__ w,
    const float* __restrict__ b0, float* __restrict__ out)
{
    const int warp = threadIdx.x >> 5;
    const int lane = threadIdx.x & 31;
    const int row  = blockIdx.x * 8 + warp;
    if (row >= M) return;
    const float* a = A + (size_t)row * K;
    float s = 0.f;
    for (int k = lane; k < K; k += 32) s = fmaf(a[k], w[k], s);
    #pragma unroll
    for (int o = 16; o > 0; o >>= 1) s += __shfl_xor_sync(0xffffffffu, s, o);
    if (lane == 0) out[row] = sigm_f(s + b0[0]);
}

// ---------------- batch mean over S: gc[b,d] = mean_s x[b,s,d] ----------------
__global__ void __launch_bounds__(256) batchmean_k(const float* __restrict__ x,
                                                   float* __restrict__ gc)
{
    const int idx = blockIdx.x * 256 + threadIdx.x;   // 0..4095
    if (idx >= Bsz * Dsz) return;
    const int b = idx >> 10, d = idx & 1023;
    const float* p = x + (size_t)b * Ssz * Dsz + d;
    float s0 = 0.f, s1 = 0.f, s2 = 0.f, s3 = 0.f;
    for (int t = 0; t < Ssz; t += 4) {
        s0 += p[(size_t)(t+0) * Dsz];
        s1 += p[(size_t)(t+1) * Dsz];
        s2 += p[(size_t)(t+2) * Dsz];
        s3 += p[(size_t)(t+3) * Dsz];
    }
    gc[idx] = (s0 + s1 + s2 + s3) * (1.0f / (float)Ssz);
}

// ---------------- mobius update: out = in + coup * twist(in) ----------------
__global__ void __launch_bounds__(256) mobius_k(const float* __restrict__ in,
    const float* __restrict__ tf, const float* __restrict__ g,
    const float* __restrict__ arng, float* __restrict__ out)
{
    const int row = blockIdx.x;           // 0..8191 = b*S+t
    const int b   = row >> 11;
    const float ar = arng[0];
    const float combined = 0.7f * g[b] + 0.3f * tf[row];
    const float coup = 0.1f + ar * (combined - 0.5f) * 2.0f;
    const float* ip = in  + (size_t)row * Dsz;
    float*       op = out + (size_t)row * Dsz;
    for (int i = threadIdx.x; i < Dsz; i += 256) {
        const int j = (i + 512) & 1023;
        const float sgn = (i < 256 || i >= 768) ? 1.0f : -1.0f;
        op[i] = ip[i] + coup * sgn * ip[j];
    }
}

// ---------------- elementwise add (float4) ----------------
__global__ void __launch_bounds__(256) add_k(const float* __restrict__ a,
                                             const float* __restrict__ b,
                                             float* __restrict__ c, int n4)
{
    const int i = blockIdx.x * 256 + threadIdx.x;
    if (i >= n4) return;
    float4 av = ((const float4*)a)[i];
    float4 bv = ((const float4*)b)[i];
    float4 cv;
    cv.x = av.x + bv.x; cv.y = av.y + bv.y; cv.z = av.z + bv.z; cv.w = av.w + bv.w;
    ((float4*)c)[i] = cv;
}

// ---------------- GRU init: zero hidden ping-pong + barrier counter ----------------
__global__ void gru_init_k()
{
    const int i = blockIdx.x * 256 + threadIdx.x;
    if (i < 2 * Bsz * Hsz) d_h[i] = 0.f;
    if (i == 0) d_bar = 0u;
}

// ---------------- persistent GRU recurrence ----------------
// 128 CTAs x 256 threads. Each CTA holds 24 W_hh rows (3 gates x 8 units) in SMEM.
// Each warp owns one hidden unit j; per step computes r/z/n dots for 4 batches.
// Barrier: release-atomic arrival + acquire poll; next-step xi prefetch is issued
// between release and poll to hide its DRAM latency under the barrier wait.
__global__ void __launch_bounds__(256, 1) gru_kernel(const float* __restrict__ xi,
    const float* __restrict__ Whh, const float* __restrict__ bhh,
    float* __restrict__ y)
{
    extern __shared__ float sm[];
    float* ws = sm;                 // 24*1024 weights
    float* hs = sm + 24 * 1024;     // 4*1024 hidden state
    const int tid   = threadIdx.x;
    const int warp  = tid >> 5;
    const int lane  = tid & 31;
    const int jbase = blockIdx.x * GRU_JPB;
    const int jg    = jbase + warp;

    // stage weights once (rows g*H + jbase + jw, g=0..2, jw=0..7)
    for (int idx = tid; idx < 24 * 256; idx += 256) {
        const int rl = idx >> 8;          // 0..23
        const int c4 = idx & 255;
        const int g  = rl >> 3, jw = rl & 7;
        const float4 v = *(const float4*)(Whh + (size_t)(g * Hsz + jbase + jw) * Hsz + c4 * 4);
        *(float4*)(ws + rl * Hsz + c4 * 4) = v;
    }
    const float bh0 = bhh[0 * Hsz + jg];
    const float bh1 = bhh[1 * Hsz + jg];
    const float bh2 = bhh[2 * Hsz + jg];
    __syncthreads();

    const float4* wr4 = (const float4*)(ws + (0 * GRU_JPB + warp) * Hsz);
    const float4* wz4 = (const float4*)(ws + (1 * GRU_JPB + warp) * Hsz);
    const float4* wn4 = (const float4*)(ws + (2 * GRU_JPB + warp) * Hsz);
    const float4* hs4 = (const float4*)hs;

    // prefetch xi for t = 0 (lanes 0..11: g = lane>>2, b = lane&3)
    float vxi = 0.f;
    if (lane < 12) {
        const int g = lane >> 2, b = lane & 3;
        vxi = xi[(size_t)(b * Ssz + 0) * (3 * Hsz) + g * Hsz + jg];
    }

    for (int t = 0; t < Ssz; t++) {
        // stage h (written by all CTAs last step) -> SMEM; .cg to bypass stale L1
        const float4* hp = (const float4*)(d_h + (t & 1) * Bsz * Hsz);
        for (int i = tid; i < Bsz * Hsz / 4; i += 256)
            *(float4*)(hs + i * 4) = __ldcg(hp + i);
        __syncthreads();

        float acc[3][4];
        #pragma unroll
        for (int g = 0; g < 3; g++)
            #pragma unroll
            for (int b = 0; b < 4; b++) acc[g][b] = 0.f;

        #pragma unroll
        for (int it = 0; it < 8; it++) {
            const int kq = lane + it * 32;          // float4 index 0..255
            const float4 wr = wr4[kq];
            const float4 wz = wz4[kq];
            const float4 wn = wn4[kq];
            #pragma unroll
            for (int b = 0; b < 4; b++) {
                const float4 h = hs4[b * 256 + kq];
                acc[0][b] += wr.x * h.x + wr.y * h.y + wr.z * h.z + wr.w * h.w;
                acc[1][b] += wz.x * h.x + wz.y * h.y + wz.z * h.z + wz.w * h.w;
                acc[2][b] += wn.x * h.x + wn.y * h.y + wn.z * h.z + wn.w * h.w;
            }
        }

        // warp reductions
        #pragma unroll
        for (int g = 0; g < 3; g++)
            #pragma unroll
            for (int b = 0; b < 4; b++)
                #pragma unroll
                for (int o = 16; o > 0; o >>= 1)
                    acc[g][b] += __shfl_xor_sync(0xffffffffu, acc[g][b], o);

        float* hn_out = d_h + ((t & 1) ^ 1) * Bsz * Hsz;
        #pragma unroll
        for (int b = 0; b < 4; b++) {
            const float xr = __shfl_sync(0xffffffffu, vxi, 0 * 4 + b);
            const float xz = __shfl_sync(0xffffffffu, vxi, 1 * 4 + b);
            const float xn = __shfl_sync(0xffffffffu, vxi, 2 * 4 + b);
            if (lane == b) {
                const float r = 1.f / (1.f + expf(-(xr + acc[0][b] + bh0)));
                const float z = 1.f / (1.f + expf(-(xz + acc[1][b] + bh1)));
                const float n = tanhf(xn + r * (acc[2][b] + bh2));
                const float hold = hs[b * Hsz + jg];
                const float hv = (1.f - z) * n + z * hold;
                hn_out[b * Hsz + jg] = hv;
                y[(size_t)(b * Ssz + t) * Hsz + jg] = hv;
            }
        }

        if (t < Ssz - 1) {
            __syncthreads();   // all warps' h writes done + hs reads complete
            // arrival: release-atomic (fence folded into the op)
            if (tid == 0)
                asm volatile("red.release.gpu.global.add.u32 [%0], %1;"
                             :: "l"(&d_bar), "r"(1u) : "memory");
            // overlap next step's xi DRAM load with the barrier wait
            float vxin = 0.f;
            if (lane < 12) {
                const int g = lane >> 2, b = lane & 3;
                vxin = xi[(size_t)(b * Ssz + (t + 1)) * (3 * Hsz) + g * Hsz + jg];
            }
            if (tid == 0) {
                const unsigned int target = (unsigned)GRU_CTAS * (unsigned)(t + 1);
                unsigned int v;
                do {
                    asm volatile("ld.acquire.gpu.u32 %0, [%1];" : "=r"(v) : "l"(&d_bar) : "memory");
                } while (v < target);
            }
            __syncthreads();
            vxi = vxin;
        }
    }
}

// ---------------- host launcher ----------------
extern "C" void kernel_launch(void* const* d_in, const int* in_sizes, int n_in,
                              void* d_out, int out_size)
{
    const float* x    = (const float*)d_in[0];
    const float* g1w  = (const float*)d_in[1];
    const float* g1b  = (const float*)d_in[2];
    const float* g2w  = (const float*)d_in[3];
    const float* g2b  = (const float*)d_in[4];
    const float* Wih0 = (const float*)d_in[5];
    const float* Whh0 = (const float*)d_in[6];
    const float* bih0 = (const float*)d_in[7];
    const float* bhh0 = (const float*)d_in[8];
    const float* Wih1 = (const float*)d_in[9];
    const float* Whh1 = (const float*)d_in[10];
    const float* bih1 = (const float*)d_in[11];
    const float* bhh1 = (const float*)d_in[12];
    const float* cw1  = (const float*)d_in[13];
    const float* cb1  = (const float*)d_in[14];
    const float* cw2  = (const float*)d_in[15];
    const float* cb2  = (const float*)d_in[16];
    const float* cw3  = (const float*)d_in[17];
    const float* cb3  = (const float*)d_in[18];
    const float* cw4  = (const float*)d_in[19];
    const float* cb4  = (const float*)d_in[20];
    const float* gw1  = (const float*)d_in[21];
    const float* gb1  = (const float*)d_in[22];
    const float* gw2  = (const float*)d_in[23];
    const float* gb2  = (const float*)d_in[24];
    const float* gw3  = (const float*)d_in[25];
    const float* gb3  = (const float*)d_in[26];
    const float* arng = (const float*)d_in[27];
    const float* fw1  = (const float*)d_in[28];
    const float* fb1  = (const float*)d_in[29];
    const float* fw2  = (const float*)d_in[30];
    const float* fb2  = (const float*)d_in[31];
    float* out = (float*)d_out;

    float *xn, *xi, *y, *x1, *m0, *m1, *c1, *c2, *c3, *tf, *gc, *g1, *g2, *gg, *f1;
    cudaGetSymbolAddress((void**)&xn, d_xn);
    cudaGetSymbolAddress((void**)&xi, d_xi);
    cudaGetSymbolAddress((void**)&y,  d_y);
    cudaGetSymbolAddress((void**)&x1, d_x1);
    cudaGetSymbolAddress((void**)&m0, d_m0);
    cudaGetSymbolAddress((void**)&m1, d_m1);
    cudaGetSymbolAddress((void**)&c1, d_c1);
    cudaGetSymbolAddress((void**)&c2, d_c2);
    cudaGetSymbolAddress((void**)&c3, d_c3);
    cudaGetSymbolAddress((void**)&tf, d_tf);
    cudaGetSymbolAddress((void**)&gc, d_gc);
    cudaGetSymbolAddress((void**)&g1, d_g1);
    cudaGetSymbolAddress((void**)&g2, d_g2);
    cudaGetSymbolAddress((void**)&gg, d_gg);
    cudaGetSymbolAddress((void**)&f1, d_f1);

    cudaFuncSetAttribute(gru_kernel, cudaFuncAttributeMaxDynamicSharedMemorySize,
                         GRU_SMEM_BYTES);

    const int n4   = TOK * Dsz / 4;
    const int addg = (n4 + 255) / 256;

    // ---- Block 1: LN -> GRU x2 -> residual ----
    ln_k<<<TOK, 256>>>(x, g1w, g1b, xn);
    sgemm_nt<<<dim3(3072/128, TOK/128), 256>>>(TOK, 3072, 1024, xn, Wih0, bih0, nullptr, xi, 0);
    gru_init_k<<<32, 256>>>();
    gru_kernel<<<GRU_CTAS, 256, GRU_SMEM_BYTES>>>(xi, Whh0, bhh0, y);
    sgemm_nt<<<dim3(3072/128, TOK/128), 256>>>(TOK, 3072, 1024, y, Wih1, bih1, nullptr, xi, 0);
    gru_init_k<<<32, 256>>>();
    gru_kernel<<<GRU_CTAS, 256, GRU_SMEM_BYTES>>>(xi, Whh1, bhh1, y);
    add_k<<<addg, 256>>>(x, y, x1, n4);

    // ---- Block 2: LN -> adaptive mobius -> residual ----
    ln_k<<<TOK, 256>>>(x1, g2w, g2b, xn);
    batchmean_k<<<(Bsz*Dsz + 255)/256, 256>>>(xn, gc);
    sgemm_nt<<<dim3(512/128, 1), 256>>>(Bsz, 512, 1024, gc, gw1, gb1, nullptr, g1, 1);
    sgemm_nt<<<dim3(256/128, 1), 256>>>(Bsz, 256, 512,  g1, gw2, gb2, nullptr, g2, 1);
    rowdot_k<<<1, 256>>>(Bsz, 256, g2, gw3, gb3, gg);

    float* cur = xn;
    float* nxt = m0;
    for (int cyc = 0; cyc < 3; cyc++) {
        sgemm_nt<<<dim3(1024/128, TOK/128), 256>>>(TOK, 1024, 1024, cur, cw1, cb1, nullptr, c1, 1);
        sgemm_nt<<<dim3(512/128,  TOK/128), 256>>>(TOK, 512,  1024, c1,  cw2, cb2, nullptr, c2, 1);
        sgemm_nt<<<dim3(256/128,  TOK/128), 256>>>(TOK, 256,  512,  c2,  cw3, cb3, nullptr, c3, 1);
        rowdot_k<<<(TOK + 7)/8, 256>>>(TOK, 256, c3, cw4, cb4, tf);
        mobius_k<<<TOK, 256>>>(cur, tf, gg, arng, nxt);
        cur = nxt;
        nxt = (cyc == 0) ? m1 : m0;
    }
    add_k<<<addg, 256>>>(x1, cur, x1, n4);   // x2 = x1 + mobius (in-place)

    // ---- Block 3: FFN residual ----
    sgemm_nt<<<dim3(4096/128, TOK/128), 256>>>(TOK, 4096, 1024, x1, fw1, fb1, nullptr, f1, 1);
    sgemm_nt<<<dim3(1024/128, TOK/128), 256>>>(TOK, 1024, 4096, f1, fw2, fb2, x1, out, 0);
}